// round 14
// baseline (speedup 1.0000x reference)
#include <cuda_runtime.h>

// Reference semantics reduce to (softmax over a size-1 axis == 1; W is dead code):
//   out[i, 0:512]    = 2*X[i]                              for i < 64
//   out[i, 0:512]    = X[i] + sum_{r=i-64..i-1} X[r]       for i >= 64
//   out[i, 512:1024] = X[i]
//
// Single fused kernel, 2 output chunks per block (read amplification 1.5x).
// Block = 192 threads = 24 segments x 8 f4 columns; seg s loads 8 rows
// [base+8s, base+8s+8), base = 64*(kfirst-1). Loaded rows 64..191 are the
// output rows (segs 8..23): right-half copy issues from registers pre-barrier,
// left half H = v[j] + (acc - Plow[m-64]). Segs 0..15 publish exclusive
// prefixes Plow. Prefix over segments: warp shfl-scan (4 segs/warp) + 6 warp
// totals via smem. Chunk 63 (odd one out) uses the same path with nch=1
// (segs 16..23 exit early).

#define NROWS 4096
#define DCOLS 512
#define LENS  64
#define D4    (DCOLS / 4)    // 128 f4 per input row
#define OD4   (2 * D4)       // 256 f4 per output row
#define CPB   8              // f4 columns per block
#define NG    (D4 / CPB)     // 16 column groups
#define SEG   8              // rows per segment/thread
#define NPAIR 31             // pair blocks cover chunks 1..62

#define NPAIRBLK (NPAIR * NG)        // 496
#define NSINGLE  NG                  // 16 (chunk 63)
#define NCOPY    NG                  // 16 (rows 0..63)
#define NBLOCKS  (NPAIRBLK + NSINGLE + NCOPY)  // 528

static __device__ __forceinline__ float4 f4add(float4 a, float4 b) {
    return make_float4(a.x + b.x, a.y + b.y, a.z + b.z, a.w + b.w);
}
static __device__ __forceinline__ float4 f4sub(float4 a, float4 b) {
    return make_float4(a.x - b.x, a.y - b.y, a.z - b.z, a.w - b.w);
}
static __device__ __forceinline__ float4 shfl_up4(float4 v, int d) {
    float4 r;
    r.x = __shfl_up_sync(0xffffffffu, v.x, d);
    r.y = __shfl_up_sync(0xffffffffu, v.y, d);
    r.z = __shfl_up_sync(0xffffffffu, v.z, d);
    r.w = __shfl_up_sync(0xffffffffu, v.w, d);
    return r;
}

__global__ __launch_bounds__(192, 5) void fused_window_kernel(
    const float4* __restrict__ X4, float4* __restrict__ O4)
{
    const int b    = blockIdx.x;
    const int tid  = threadIdx.x;
    const int c    = tid & 7;          // column within group
    const int s    = tid >> 3;         // segment 0..23
    const int w    = tid >> 5;         // warp 0..5
    const int lane = tid & 31;

    int g, base, nch;
    if (b < NPAIRBLK) {                       // chunks 2p+1, 2p+2
        const int p = b >> 4;
        g    = b & 15;
        base = p * 128;                       // = 64*(2p+1 - 1)
        nch  = 2;
    } else if (b < NPAIRBLK + NSINGLE) {      // chunk 63
        g    = b - NPAIRBLK;
        base = 62 * LENS;                     // 3968
        nch  = 1;
    } else {                                  // rows 0..63 copy
        g = b - NPAIRBLK - NSINGLE;
        const int col = g * CPB + c;
        if (s < 16) {
            #pragma unroll
            for (int r = 0; r < 4; ++r) {
                const int i = s * 4 + r;
                float4 x = X4[(size_t)i * D4 + col];
                O4[(size_t)i * OD4 + col]      = f4add(x, x);
                O4[(size_t)i * OD4 + D4 + col] = x;
            }
        }
        return;
    }

    const int nseg = 8 * (nch + 1);           // 24 or 16
    if (s >= nseg) return;                    // exited threads skip barriers (legal)
    const int col = g * CPB + c;

    __shared__ float4 wtot[6 * CPB];          // per-warp totals (768 B)
    __shared__ float4 Plow[128 * CPB];        // exclusive prefixes P[0..127] (16 KB)

    // ---- Load: 8 independent LDG.128; rows base + s*8 + j ----
    const float4* px = X4 + (size_t)(base + s * SEG) * D4 + col;
    float4 v[SEG];
    #pragma unroll
    for (int j = 0; j < SEG; ++j) v[j] = px[(size_t)j * D4];

    // Emitters (s >= 8): right-half copy from registers, pre-barrier.
    if (s >= 8) {
        float4* po = O4 + (size_t)(base + s * SEG) * OD4 + D4 + col;
        #pragma unroll
        for (int j = 0; j < SEG; ++j)
            po[(size_t)j * OD4] = v[j];
    }

    // Segment total (tree of 8).
    float4 s01 = f4add(v[0], v[1]);
    float4 s23 = f4add(v[2], v[3]);
    float4 s45 = f4add(v[4], v[5]);
    float4 s67 = f4add(v[6], v[7]);
    float4 ls  = f4add(f4add(s01, s23), f4add(s45, s67));

    // Within-warp inclusive scan over the warp's 4 segments (strides 8, 16).
    float4 inc = ls;
    {
        float4 t = shfl_up4(inc, 8);
        if (lane >= 8) inc = f4add(inc, t);
        t = shfl_up4(inc, 16);
        if (lane >= 16) inc = f4add(inc, t);
    }
    if (lane >= 24) wtot[w * CPB + c] = inc;   // warp total
    __syncthreads();

    // Exclusive prefix of segment s: within-warp exclusive + warp totals below.
    float4 off = f4sub(inc, ls);               // exact 0 for first seg of warp 0
    #pragma unroll
    for (int jw = 0; jw < 5; ++jw) {
        float4 t = wtot[jw * CPB + c];
        if (w > jw) off = f4add(off, t);
    }

    // Publish exclusive row-prefixes P[s*8+j] for consumers 8 segs above.
    if (s < 8 * nch) {
        float4 acc = off;
        float4* pp = Plow + (s * SEG) * CPB + c;
        #pragma unroll
        for (int j = 0; j < SEG; ++j) {
            pp[j * CPB] = acc;
            acc = f4add(acc, v[j]);
        }
    }
    __syncthreads();

    // Emit left half: loaded row m = s*8+j, output row i = base+m.
    //   W = P[m] - P[m-64];  P[m] = acc before adding v[j]; P[m-64] from Plow.
    if (s >= 8) {
        float4 acc = off;
        const float4* pl = Plow + ((s - 8) * SEG) * CPB + c;
        float4* po = O4 + (size_t)(base + s * SEG) * OD4 + col;
        #pragma unroll
        for (int j = 0; j < SEG; ++j) {
            float4 wsum = f4sub(acc, pl[j * CPB]);
            po[(size_t)j * OD4] = f4add(v[j], wsum);
            acc = f4add(acc, v[j]);
        }
    }
}

extern "C" void kernel_launch(void* const* d_in, const int* in_sizes, int n_in,
                              void* d_out, int out_size)
{
    const float4* X4 = (const float4*)d_in[0];   // X: (4096, 512) f32
    float4* O4 = (float4*)d_out;                 // out: (4096, 1024) f32

    fused_window_kernel<<<NBLOCKS, 192>>>(X4, O4);   // 528 blocks, 1 launch
}

// round 17
// speedup vs baseline: 1.0295x; 1.0295x over previous
#include <cuda_runtime.h>

// Reference semantics reduce to (softmax over a size-1 axis == 1; W is dead code):
//   out[i, 0:512]    = 2*X[i]                              for i < 64
//   out[i, 0:512]    = X[i] + sum_{r=i-64..i-1} X[r]       for i >= 64
//   out[i, 512:1024] = X[i]
//
// Tile = (chunk k of 64 output rows) x (4 f4 columns). Block = 64 threads
// (2 warps): warp0 owns loaded rows 0..63 (publishes exclusive prefixes),
// warp1 owns rows 64..127 == the output rows (right-half copy from registers
// pre-barrier; left half H = v[j] + (acc - Plow[m-64])). Prefix over segments:
// 3-step warp shfl scan + ONE smem warp-total read. 2048 small blocks ->
// ~14 independent pipelines per SM, single wave.

#define NROWS 4096
#define DCOLS 512
#define LENS  64
#define D4    (DCOLS / 4)   // 128 f4 per input row
#define OD4   (2 * D4)      // 256 f4 per output row
#define CPB   4             // f4 columns per block
#define NGRP  32            // column groups
#define SEG   8             // rows per segment/thread

static __device__ __forceinline__ float4 f4add(float4 a, float4 b) {
    return make_float4(a.x + b.x, a.y + b.y, a.z + b.z, a.w + b.w);
}
static __device__ __forceinline__ float4 f4sub(float4 a, float4 b) {
    return make_float4(a.x - b.x, a.y - b.y, a.z - b.z, a.w - b.w);
}
static __device__ __forceinline__ float4 shfl_up4(float4 v, int d) {
    float4 r;
    r.x = __shfl_up_sync(0xffffffffu, v.x, d);
    r.y = __shfl_up_sync(0xffffffffu, v.y, d);
    r.z = __shfl_up_sync(0xffffffffu, v.z, d);
    r.w = __shfl_up_sync(0xffffffffu, v.w, d);
    return r;
}

// Plow layout: entry for loaded row m = s*8 + j (s in 0..7) stored at
// index ((j*8 + s)*CPB + c). Within an 8-lane smem phase (s, s+1 x c=0..3)
// banks are (s*16 + c*4) % 32 -> all distinct: conflict-free.
#define PIDX(s, j, c) ((((j) * 8 + (s)) * CPB) + (c))

__global__ __launch_bounds__(64, 14) void fused_window_kernel(
    const float4* __restrict__ X4, float4* __restrict__ O4)
{
    const int b    = blockIdx.x;
    const int k    = b >> 5;          // chunk 0..63
    const int g    = b & 31;          // column group 0..31
    const int tid  = threadIdx.x;
    const int c    = tid & 3;         // column within group
    const int s    = tid >> 2;        // segment 0..15
    const int w    = tid >> 5;        // warp 0..1
    const int lane = tid & 31;
    const int col  = g * CPB + c;     // global f4 column

    if (k == 0) {
        // rows 0..63: left = 2X, right = X. Thread handles rows s*4..s*4+3.
        #pragma unroll
        for (int r = 0; r < 4; ++r) {
            const int i = s * 4 + r;
            float4 x = X4[(size_t)i * D4 + col];
            O4[(size_t)i * OD4 + col]      = f4add(x, x);
            O4[(size_t)i * OD4 + D4 + col] = x;
        }
        return;
    }

    __shared__ float4 Plow[LENS * CPB];   // exclusive prefixes for rows 0..63 (4 KB)
    __shared__ float4 wtot[CPB];          // warp0 total (64 B)

    // ---- Load: 8 independent LDG.128; rows base + s*8 + j ----
    const int base = (k - 1) * LENS;
    const float4* px = X4 + (size_t)(base + s * SEG) * D4 + col;
    float4 v[SEG];
    #pragma unroll
    for (int j = 0; j < SEG; ++j) v[j] = px[(size_t)j * D4];

    // Warp1: right-half copy from registers, pre-barrier (pure overlap).
    if (w == 1) {
        float4* po = O4 + (size_t)(base + s * SEG) * OD4 + D4 + col;
        #pragma unroll
        for (int j = 0; j < SEG; ++j)
            po[(size_t)j * OD4] = v[j];
    }

    // Segment total (tree of 8).
    float4 s01 = f4add(v[0], v[1]);
    float4 s23 = f4add(v[2], v[3]);
    float4 s45 = f4add(v[4], v[5]);
    float4 s67 = f4add(v[6], v[7]);
    float4 ls  = f4add(f4add(s01, s23), f4add(s45, s67));

    // Within-warp inclusive scan over the warp's 8 segments (strides 4, 8, 16).
    float4 inc = ls;
    {
        float4 t = shfl_up4(inc, 4);
        if (lane >= 4) inc = f4add(inc, t);
        t = shfl_up4(inc, 8);
        if (lane >= 8) inc = f4add(inc, t);
        t = shfl_up4(inc, 16);
        if (lane >= 16) inc = f4add(inc, t);
    }
    float4 off = f4sub(inc, ls);      // within-warp exclusive (exact 0 for seg 0)

    if (w == 0) {
        // Publish warp total + exclusive row-prefixes P[s*8+j] (conflict-free layout).
        if (lane >= 28) wtot[c] = inc;     // seg 7's inclusive value = warp0 total
        float4 acc = off;
        #pragma unroll
        for (int j = 0; j < SEG; ++j) {
            Plow[PIDX(s, j, c)] = acc;
            acc = f4add(acc, v[j]);
        }
    }
    __syncthreads();

    if (w == 1) {
        // Emit left half: loaded row m = s*8+j, output row i = base+m.
        //   P[m]   = warp0_total + within-warp-exclusive + sum v[..j-1]  (= acc)
        //   W      = P[m] - Plow[m-64];  H = v[j] + W
        float4 acc = f4add(off, wtot[c]);
        const int sl = s - 8;
        float4* po = O4 + (size_t)(base + s * SEG) * OD4 + col;
        #pragma unroll
        for (int j = 0; j < SEG; ++j) {
            float4 wsum = f4sub(acc, Plow[PIDX(sl, j, c)]);
            po[(size_t)j * OD4] = f4add(v[j], wsum);
            acc = f4add(acc, v[j]);
        }
    }
}

extern "C" void kernel_launch(void* const* d_in, const int* in_sizes, int n_in,
                              void* d_out, int out_size)
{
    const float4* X4 = (const float4*)d_in[0];   // X: (4096, 512) f32
    float4* O4 = (float4*)d_out;                 // out: (4096, 1024) f32

    // 64 chunks x 32 column groups = 2048 blocks of 64 threads, 1 launch.
    fused_window_kernel<<<64 * NGRP, 64>>>(X4, O4);
}